// round 9
// baseline (speedup 1.0000x reference)
#include <cuda_runtime.h>
#include <cuda.h>
#include <cstdint>

// ============================================================================
// SpikingLinearLayer — int8 3-plane IMMA GEMM (TMA pipeline) + LIF scan
//   w = 2^-7 q0 + 2^-15 q1 + 2^-23 q2  (int8 planes, exact s32 accumulation)
//   x binary -> int8 exact. c = 2^-7 S0 + 2^-15 S1 + 2^-23 S2 (exact cvt).
// ============================================================================

namespace {

constexpr int T_STEPS = 20;
constexpr int BATCH   = 1024;
constexpr int IN_DIM  = 2048;
constexpr int OUT_DIM = 2048;
constexpr int M_TOTAL = T_STEPS * BATCH;     // 20480
constexpr int PLANES  = 3;
constexpr int K3      = PLANES * IN_DIM;     // 6144

constexpr float ALPHA_S = 0.8f;
constexpr float ALPHA_M = 0.95f;
constexpr float DT_TAUM = 0.05f;
constexpr float S0F = 0.0078125f;            // 2^-7
constexpr float S1F = 3.0517578125e-5f;      // 2^-15
constexpr float S2F = 1.1920928955078125e-7f;// 2^-23

__device__ __align__(1024) int8_t g_x_i8[(size_t)M_TOTAL * IN_DIM];   // 42 MB
__device__ __align__(1024) int8_t g_w3[(size_t)OUT_DIM * K3];         // 12.6 MB
__device__ __align__(1024) float  g_cur[(size_t)M_TOTAL * OUT_DIM];   // 168 MB

__device__ __forceinline__ uint32_t smem_u32(const void* p) {
    uint32_t a;
    asm("{ .reg .u64 t; cvta.to.shared.u64 t, %1; cvt.u32.u64 %0, t; }"
        : "=r"(a) : "l"(p));
    return a;
}

#define MBAR_INIT(addr, cnt) \
    asm volatile("mbarrier.init.shared.b64 [%0], %1;" :: "r"(addr), "r"(cnt) : "memory")
#define MBAR_ARRIVE(addr) \
    asm volatile("mbarrier.arrive.shared.b64 _, [%0];" :: "r"(addr) : "memory")
#define MBAR_EXPECT_TX(addr, bytes) \
    asm volatile("mbarrier.arrive.expect_tx.shared.b64 _, [%0], %1;" \
        :: "r"(addr), "r"(bytes) : "memory")
#define MBAR_WAIT(addr, ph) do {                                                   \
    uint32_t _m = (addr), _p = (ph), _d;                                           \
    asm volatile("{\n\t.reg .pred p;\n\t"                                          \
        "mbarrier.try_wait.parity.acquire.cta.shared::cta.b64 p, [%1], %2;\n\t"    \
        "selp.b32 %0, 1, 0, p;\n\t}" : "=r"(_d) : "r"(_m), "r"(_p) : "memory");    \
    if (!_d) {                                                                     \
        asm volatile("{\n\t.reg .pred P;\n\t"                                      \
        "WL_%=:\n\t"                                                               \
        "mbarrier.try_wait.parity.acquire.cta.shared::cta.b64 P, [%0], %1, 0x989680;\n\t" \
        "@P bra.uni WD_%=;\n\t"                                                    \
        "bra.uni WL_%=;\n\t"                                                       \
        "WD_%=:\n\t}" :: "r"(_m), "r"(_p) : "memory");                             \
    }                                                                              \
} while (0)

#define TMA_LOAD_2D(dst, map_addr, c0, c1, mbar) \
    asm volatile( \
        "cp.async.bulk.tensor.2d.shared::cta.global.tile.mbarrier::complete_tx::bytes " \
        "[%0], [%1, {%2, %3}], [%4];" \
        :: "r"(dst), "l"(map_addr), "r"(c0), "r"(c1), "r"(mbar) : "memory")

__device__ __forceinline__ void ldsm4(uint32_t& r0, uint32_t& r1, uint32_t& r2,
                                      uint32_t& r3, uint32_t addr) {
    asm volatile("ldmatrix.sync.aligned.m8n8.x4.shared.b16 {%0,%1,%2,%3}, [%4];"
                 : "=r"(r0), "=r"(r1), "=r"(r2), "=r"(r3) : "r"(addr));
}

// int8 IMMA: D(s32) += A(s8) * B(s8);  m16n8k32
__device__ __forceinline__ void imma16832(int32_t* d, uint32_t a0, uint32_t a1,
                                          uint32_t a2, uint32_t a3,
                                          uint32_t b0, uint32_t b1) {
    asm volatile(
        "mma.sync.aligned.m16n8k32.row.col.s32.s8.s8.s32 "
        "{%0,%1,%2,%3}, {%4,%5,%6,%7}, {%8,%9}, {%0,%1,%2,%3};"
        : "+r"(d[0]), "+r"(d[1]), "+r"(d[2]), "+r"(d[3])
        : "r"(a0), "r"(a1), "r"(a2), "r"(a3), "r"(b0), "r"(b1));
}

// ============================================================================
// Stage A: x fp32(binary) -> int8 {0,1}
// ============================================================================
__global__ void convert_x_kernel(const float* __restrict__ x) {
    size_t i = ((size_t)blockIdx.x * blockDim.x + threadIdx.x) * 4;
    float4 v = *reinterpret_cast<const float4*>(x + i);
    uint32_t p = (uint32_t)(v.x != 0.0f) | ((uint32_t)(v.y != 0.0f) << 8) |
                 ((uint32_t)(v.z != 0.0f) << 16) | ((uint32_t)(v.w != 0.0f) << 24);
    *reinterpret_cast<uint32_t*>(g_x_i8 + i) = p;
}

// ============================================================================
// Stage B: w -> 3 int8 planes (scales 2^-7, 2^-15, 2^-23), concat along K
// ============================================================================
__global__ void convert_w_kernel(const float* __restrict__ w) {
    size_t i = ((size_t)blockIdx.x * blockDim.x + threadIdx.x) * 4;
    int o = (int)(i / IN_DIM);
    int k = (int)(i % IN_DIM);
    float4 v = *reinterpret_cast<const float4*>(w + i);
    float vv[4] = {v.x, v.y, v.z, v.w};
    uint32_t q0p = 0, q1p = 0, q2p = 0;
#pragma unroll
    for (int j = 0; j < 4; j++) {
        float f = vv[j];
        int q0 = __float2int_rn(f * 128.0f);
        q0 = max(-127, min(127, q0));
        float r1 = f - (float)q0 * S0F;
        int q1 = __float2int_rn(r1 * 32768.0f);
        q1 = max(-127, min(127, q1));
        float r2 = r1 - (float)q1 * S1F;
        int q2 = __float2int_rn(r2 * 8388608.0f);
        q2 = max(-127, min(127, q2));
        q0p |= ((uint32_t)q0 & 0xFF) << (j * 8);
        q1p |= ((uint32_t)q1 & 0xFF) << (j * 8);
        q2p |= ((uint32_t)q2 & 0xFF) << (j * 8);
    }
    int8_t* base = g_w3 + (size_t)o * K3 + k;
    *reinterpret_cast<uint32_t*>(base)              = q0p;
    *reinterpret_cast<uint32_t*>(base + IN_DIM)     = q1p;
    *reinterpret_cast<uint32_t*>(base + 2 * IN_DIM) = q2p;
}

// ============================================================================
// Stage C: GEMM  S_p = X_i8 * Q_p^T ; c = 2^-7 S0 + 2^-15 S1 + 2^-23 S2
//   CTA 128x128, 8 warps @ 64x32, BK=128 int8, 3-stage TMA pipeline.
// ============================================================================
constexpr int TILE_M = 128;
constexpr int TILE_N = 128;
constexpr int BK     = 128;              // int8 elements = 128 bytes/row
constexpr int NTH    = 256;
constexpr int KITERS = IN_DIM / BK;      // 16
constexpr int STAGES = 3;

constexpr int A_BYTES = TILE_M * BK;     // 16384
constexpr int B_BYTES = TILE_N * BK;     // 16384 per plane
constexpr int STAGE_BYTES = A_BYTES + PLANES * B_BYTES;  // 65536
constexpr int SMEM_BYTES  = 1024 + STAGES * STAGE_BYTES; // 197632

__global__ void __launch_bounds__(NTH, 1)
snn_gemm_kernel(const __grid_constant__ CUtensorMap tma_a,
                const __grid_constant__ CUtensorMap tma_b,
                float* __restrict__ cbuf) {
    extern __shared__ char smem_raw[];
    const uint32_t sbase = (smem_u32(smem_raw) + 1023) & ~1023u;
    const uint32_t stg_base = sbase + 1024;

    const int tid  = threadIdx.x;
    const int lane = tid & 31;
    const int wid  = tid >> 5;
    const int mw   = wid >> 2;       // 0..1 -> 64-row band
    const int nwp  = wid & 3;        // 0..3 -> 32-col band
    const int bid  = blockIdx.x;
    const int m0   = (bid >> 4) * TILE_M;   // 160 m-blocks
    const int n0   = (bid & 15) * TILE_N;   // 16 n-blocks (W stays in L2)

    if (tid == 0) {
#pragma unroll
        for (int s = 0; s < STAGES; s++) {
            MBAR_INIT(sbase + s * 8, 1);         // full: tx-based
            MBAR_INIT(sbase + 32 + s * 8, 8);    // empty: one arrive per warp
        }
    }
    __syncthreads();

    const uint64_t map_a = (uint64_t)&tma_a;
    const uint64_t map_b = (uint64_t)&tma_b;

    auto load_stage = [&](int kc) {
        const int s = kc % STAGES;
        const uint32_t stg = stg_base + s * STAGE_BYTES;
        const uint32_t mb = sbase + s * 8;
        MBAR_EXPECT_TX(mb, STAGE_BYTES);
        TMA_LOAD_2D(stg, map_a, kc * BK, m0, mb);
#pragma unroll
        for (int p = 0; p < PLANES; p++)
            TMA_LOAD_2D(stg + A_BYTES + p * B_BYTES, map_b,
                        p * IN_DIM + kc * BK, n0, mb);
    };

    if (tid == 0) {
        load_stage(0); load_stage(1); load_stage(2);
    }

    const int lr = lane & 15;
    const int halfsel = (lane >> 4) * 16;
    uint32_t a_rowoff[4], a_xr[4];
#pragma unroll
    for (int mt = 0; mt < 4; mt++) {
        int r = mw * 64 + mt * 16 + lr;
        a_rowoff[mt] = r * 128;
        a_xr[mt] = (r & 7) * 16;
    }
    uint32_t b_rowoff[2], b_xr[2];
#pragma unroll
    for (int nt = 0; nt < 2; nt++) {
        int r = nwp * 32 + nt * 16 + lr;
        b_rowoff[nt] = r * 128;
        b_xr[nt] = (r & 7) * 16;
    }

    int32_t acc[PLANES][4][4][4];   // [plane][mt][n8][4] s32
#pragma unroll
    for (int p = 0; p < PLANES; p++)
#pragma unroll
        for (int i = 0; i < 4; i++)
#pragma unroll
            for (int j = 0; j < 4; j++)
#pragma unroll
                for (int q = 0; q < 4; q++) acc[p][i][j][q] = 0;

    int pf[STAGES] = {0, 0, 0}, pe[STAGES] = {0, 0, 0};

    for (int kc = 0; kc < KITERS; kc++) {
        const int s = kc % STAGES;
        const uint32_t stg = stg_base + s * STAGE_BYTES;
        MBAR_WAIT(sbase + s * 8, pf[s]);
        pf[s] ^= 1;

#pragma unroll
        for (int kk = 0; kk < 4; kk++) {        // 4 x k32 = BK 128
            const uint32_t kb = kk * 32 + halfsel;
            uint32_t a[4][4];
#pragma unroll
            for (int mt = 0; mt < 4; mt++)
                ldsm4(a[mt][0], a[mt][1], a[mt][2], a[mt][3],
                      stg + a_rowoff[mt] + (kb ^ a_xr[mt]));
#pragma unroll
            for (int p = 0; p < PLANES; p++) {
                const uint32_t bb = stg + A_BYTES + p * B_BYTES;
#pragma unroll
                for (int nt = 0; nt < 2; nt++) {
                    uint32_t b0, b1, b2, b3;
                    ldsm4(b0, b1, b2, b3, bb + b_rowoff[nt] + (kb ^ b_xr[nt]));
#pragma unroll
                    for (int mt = 0; mt < 4; mt++) {
                        imma16832(acc[p][mt][nt * 2 + 0], a[mt][0], a[mt][1],
                                  a[mt][2], a[mt][3], b0, b2);
                        imma16832(acc[p][mt][nt * 2 + 1], a[mt][0], a[mt][1],
                                  a[mt][2], a[mt][3], b1, b3);
                    }
                }
            }
        }

        if (lane == 0) MBAR_ARRIVE(sbase + 32 + s * 8);
        if (tid == 0 && kc + STAGES < KITERS) {
            MBAR_WAIT(sbase + 32 + s * 8, pe[s]);
            pe[s] ^= 1;
            load_stage(kc + STAGES);
        }
    }

    // ---- epilogue: c = 2^-7 S0 + 2^-15 S1 + 2^-23 S2 ----
    const int mrow = m0 + mw * 64 + (lane >> 2);
    const int ncol = n0 + nwp * 32 + (lane & 3) * 2;
#pragma unroll
    for (int mt = 0; mt < 4; mt++) {
        float* r0 = cbuf + (size_t)(mrow + mt * 16) * OUT_DIM + ncol;
        float* r1 = r0 + 8 * OUT_DIM;
#pragma unroll
        for (int j = 0; j < 4; j++) {
            float c[4];
#pragma unroll
            for (int q = 0; q < 4; q++) {
                c[q] = fmaf((float)acc[0][mt][j][q], S0F,
                       fmaf((float)acc[1][mt][j][q], S1F,
                            (float)acc[2][mt][j][q] * S2F));
            }
            *reinterpret_cast<float2*>(r0 + j * 8) = make_float2(c[0], c[1]);
            *reinterpret_cast<float2*>(r1 + j * 8) = make_float2(c[2], c[3]);
        }
    }
}

// ============================================================================
// Stage D: LIF scan over t (memory bound)
// ============================================================================
__global__ void lif_scan_kernel(const float* __restrict__ cbuf,
                                float* __restrict__ out) {
    const size_t idx4 = ((size_t)blockIdx.x * blockDim.x + threadIdx.x) * 4;
    float4 V = make_float4(0.f, 0.f, 0.f, 0.f);
    float4 I = make_float4(0.f, 0.f, 0.f, 0.f);
#pragma unroll
    for (int t = 0; t < T_STEPS; t++) {
        const size_t off = (size_t)t * BATCH * OUT_DIM + idx4;
        float4 c = *reinterpret_cast<const float4*>(cbuf + off);
        float4 s;
        I.x = ALPHA_S * I.x + c.x;  V.x = ALPHA_M * V.x + DT_TAUM * I.x;
        s.x = (V.x >= 1.0f) ? 1.0f : 0.0f;  V.x *= (1.0f - s.x);
        I.y = ALPHA_S * I.y + c.y;  V.y = ALPHA_M * V.y + DT_TAUM * I.y;
        s.y = (V.y >= 1.0f) ? 1.0f : 0.0f;  V.y *= (1.0f - s.y);
        I.z = ALPHA_S * I.z + c.z;  V.z = ALPHA_M * V.z + DT_TAUM * I.z;
        s.z = (V.z >= 1.0f) ? 1.0f : 0.0f;  V.z *= (1.0f - s.z);
        I.w = ALPHA_S * I.w + c.w;  V.w = ALPHA_M * V.w + DT_TAUM * I.w;
        s.w = (V.w >= 1.0f) ? 1.0f : 0.0f;  V.w *= (1.0f - s.w);
        *reinterpret_cast<float4*>(out + off) = s;
    }
}

}  // namespace

// ---- host-side tensormap setup (rebuilt every call; no static guards) ----
typedef CUresult (*PFN_cuTensorMapEncodeTiled)(
    CUtensorMap*, CUtensorMapDataType, cuuint32_t, void*,
    const cuuint64_t*, const cuuint64_t*, const cuuint32_t*, const cuuint32_t*,
    CUtensorMapInterleave, CUtensorMapSwizzle, CUtensorMapL2promotion,
    CUtensorMapFloatOOBfill);

static CUtensorMap s_tma_a, s_tma_b;

static void build_tensormaps() {
    PFN_cuTensorMapEncodeTiled encode = nullptr;
    cudaDriverEntryPointQueryResult qres;
    cudaGetDriverEntryPoint("cuTensorMapEncodeTiled", (void**)&encode,
                            cudaEnableDefault, &qres);
    if (!encode) return;
    void* xa; cudaGetSymbolAddress(&xa, g_x_i8);
    void* wa; cudaGetSymbolAddress(&wa, g_w3);

    {   // A: [2048 x 20480] int8, box [128 x 128]
        cuuint64_t dims[2]    = {(cuuint64_t)IN_DIM, (cuuint64_t)M_TOTAL};
        cuuint64_t strides[1] = {(cuuint64_t)IN_DIM};
        cuuint32_t box[2]     = {BK, TILE_M};
        cuuint32_t es[2]      = {1, 1};
        encode(&s_tma_a, CU_TENSOR_MAP_DATA_TYPE_UINT8, 2, xa,
               dims, strides, box, es,
               CU_TENSOR_MAP_INTERLEAVE_NONE, CU_TENSOR_MAP_SWIZZLE_128B,
               CU_TENSOR_MAP_L2_PROMOTION_L2_128B,
               CU_TENSOR_MAP_FLOAT_OOB_FILL_NONE);
    }
    {   // B: [6144 x 2048] int8, box [128 x 128]
        cuuint64_t dims[2]    = {(cuuint64_t)K3, (cuuint64_t)OUT_DIM};
        cuuint64_t strides[1] = {(cuuint64_t)K3};
        cuuint32_t box[2]     = {BK, TILE_N};
        cuuint32_t es[2]      = {1, 1};
        encode(&s_tma_b, CU_TENSOR_MAP_DATA_TYPE_UINT8, 2, wa,
               dims, strides, box, es,
               CU_TENSOR_MAP_INTERLEAVE_NONE, CU_TENSOR_MAP_SWIZZLE_128B,
               CU_TENSOR_MAP_L2_PROMOTION_L2_128B,
               CU_TENSOR_MAP_FLOAT_OOB_FILL_NONE);
    }
}

extern "C" void kernel_launch(void* const* d_in, const int* in_sizes, int n_in,
                              void* d_out, int out_size) {
    const float* x = (const float*)d_in[0];   // [T, B, IN]
    const float* w = (const float*)d_in[1];   // [OUT, IN]
    float* out = (float*)d_out;               // [T, B, OUT]

    build_tensormaps();
    float* cbuf;
    cudaGetSymbolAddress((void**)&cbuf, g_cur);

    convert_x_kernel<<<(int)((size_t)M_TOTAL * IN_DIM / 4 / 256), 256>>>(x);
    convert_w_kernel<<<(int)((size_t)OUT_DIM * IN_DIM / 4 / 256), 256>>>(w);

    cudaFuncSetAttribute(snn_gemm_kernel,
                         cudaFuncAttributeMaxDynamicSharedMemorySize, SMEM_BYTES);
    snn_gemm_kernel<<<(M_TOTAL / TILE_M) * (OUT_DIM / TILE_N), NTH, SMEM_BYTES>>>(
        s_tma_a, s_tma_b, cbuf);

    lif_scan_kernel<<<(int)((size_t)BATCH * OUT_DIM / 4 / 256), 256>>>(cbuf, out);
}

// round 10
// speedup vs baseline: 3.9096x; 3.9096x over previous
#include <cuda_runtime.h>
#include <cuda.h>
#include <cuda_fp16.h>
#include <cstdint>

// ============================================================================
// SpikingLinearLayer — fp16 2-plane GEMM (TMA, 2 CTAs/SM, small warp tile)
//   Plane 0 (hi):       f32-accumulate HMMA
//   Plane 1 (residual): scaled 2^10, f16-accumulate HMMA, folded in epilogue
//   R10: CTA 128x64, warp tile 64x16 (~100 regs), 3-stage pipeline, 2 CTAs/SM.
// ============================================================================

namespace {

constexpr int T_STEPS = 20;
constexpr int BATCH   = 1024;
constexpr int IN_DIM  = 2048;
constexpr int OUT_DIM = 2048;
constexpr int M_TOTAL = T_STEPS * BATCH;     // 20480
constexpr int K_CAT   = 2 * IN_DIM;          // 4096

constexpr float ALPHA_S = 0.8f;
constexpr float ALPHA_M = 0.95f;
constexpr float DT_TAUM = 0.05f;
constexpr float P1_SCALE    = 1024.0f;
constexpr float P1_INVSCALE = 0.0009765625f;   // 2^-10

__device__ __align__(1024) __half g_x_f16[(size_t)M_TOTAL * IN_DIM];   // 84 MB
__device__ __align__(1024) __half g_w_cat[(size_t)OUT_DIM * K_CAT];    // 17 MB
__device__ __align__(1024) float  g_cur[(size_t)M_TOTAL * OUT_DIM];    // 168 MB

__device__ __forceinline__ uint32_t smem_u32(const void* p) {
    uint32_t a;
    asm("{ .reg .u64 t; cvta.to.shared.u64 t, %1; cvt.u32.u64 %0, t; }"
        : "=r"(a) : "l"(p));
    return a;
}

#define MBAR_INIT(addr, cnt) \
    asm volatile("mbarrier.init.shared.b64 [%0], %1;" :: "r"(addr), "r"(cnt) : "memory")
#define MBAR_ARRIVE(addr) \
    asm volatile("mbarrier.arrive.shared.b64 _, [%0];" :: "r"(addr) : "memory")
#define MBAR_EXPECT_TX(addr, bytes) \
    asm volatile("mbarrier.arrive.expect_tx.shared.b64 _, [%0], %1;" \
        :: "r"(addr), "r"(bytes) : "memory")
#define MBAR_WAIT(addr, ph) do {                                                   \
    uint32_t _m = (addr), _p = (ph), _d;                                           \
    asm volatile("{\n\t.reg .pred p;\n\t"                                          \
        "mbarrier.try_wait.parity.acquire.cta.shared::cta.b64 p, [%1], %2;\n\t"    \
        "selp.b32 %0, 1, 0, p;\n\t}" : "=r"(_d) : "r"(_m), "r"(_p) : "memory");    \
    if (!_d) {                                                                     \
        asm volatile("{\n\t.reg .pred P;\n\t"                                      \
        "WL_%=:\n\t"                                                               \
        "mbarrier.try_wait.parity.acquire.cta.shared::cta.b64 P, [%0], %1, 0x989680;\n\t" \
        "@P bra.uni WD_%=;\n\t"                                                    \
        "bra.uni WL_%=;\n\t"                                                       \
        "WD_%=:\n\t}" :: "r"(_m), "r"(_p) : "memory");                             \
    }                                                                              \
} while (0)

#define TMA_LOAD_2D(dst, map_addr, c0, c1, mbar) \
    asm volatile( \
        "cp.async.bulk.tensor.2d.shared::cta.global.tile.mbarrier::complete_tx::bytes " \
        "[%0], [%1, {%2, %3}], [%4];" \
        :: "r"(dst), "l"(map_addr), "r"(c0), "r"(c1), "r"(mbar) : "memory")

__device__ __forceinline__ void ldsm4(uint32_t& r0, uint32_t& r1, uint32_t& r2,
                                      uint32_t& r3, uint32_t addr) {
    asm volatile("ldmatrix.sync.aligned.m8n8.x4.shared.b16 {%0,%1,%2,%3}, [%4];"
                 : "=r"(r0), "=r"(r1), "=r"(r2), "=r"(r3) : "r"(addr));
}

__device__ __forceinline__ void mma16816(float* d, uint32_t a0, uint32_t a1,
                                         uint32_t a2, uint32_t a3,
                                         uint32_t b0, uint32_t b1) {
    asm volatile(
        "mma.sync.aligned.m16n8k16.row.col.f32.f16.f16.f32 "
        "{%0,%1,%2,%3}, {%4,%5,%6,%7}, {%8,%9}, {%0,%1,%2,%3};"
        : "+f"(d[0]), "+f"(d[1]), "+f"(d[2]), "+f"(d[3])
        : "r"(a0), "r"(a1), "r"(a2), "r"(a3), "r"(b0), "r"(b1));
}

__device__ __forceinline__ void mma16816_h(uint32_t* d, uint32_t a0, uint32_t a1,
                                           uint32_t a2, uint32_t a3,
                                           uint32_t b0, uint32_t b1) {
    asm volatile(
        "mma.sync.aligned.m16n8k16.row.col.f16.f16.f16.f16 "
        "{%0,%1}, {%2,%3,%4,%5}, {%6,%7}, {%0,%1};"
        : "+r"(d[0]), "+r"(d[1])
        : "r"(a0), "r"(a1), "r"(a2), "r"(a3), "r"(b0), "r"(b1));
}

// ============================================================================
// Stage A: x fp32 -> fp16  (binary values: exact)
// ============================================================================
__global__ void convert_x_kernel(const float* __restrict__ x) {
    size_t i = ((size_t)blockIdx.x * blockDim.x + threadIdx.x) * 4;
    float4 v = *reinterpret_cast<const float4*>(x + i);
    __half2 lo = __floats2half2_rn(v.x, v.y);
    __half2 hi = __floats2half2_rn(v.z, v.w);
    uint2 packed = make_uint2(*reinterpret_cast<uint32_t*>(&lo),
                              *reinterpret_cast<uint32_t*>(&hi));
    *reinterpret_cast<uint2*>(g_x_f16 + i) = packed;
}

// ============================================================================
// Stage B: w -> plane0 fp16(w), plane1 fp16(1024*(w - plane0)); concat on K
// ============================================================================
__global__ void convert_w_kernel(const float* __restrict__ w) {
    size_t i = ((size_t)blockIdx.x * blockDim.x + threadIdx.x) * 4;
    int o = (int)(i / IN_DIM);
    int k = (int)(i % IN_DIM);
    float4 v = *reinterpret_cast<const float4*>(w + i);
    float vv[4] = {v.x, v.y, v.z, v.w};
    __half p0[4], p1[4];
#pragma unroll
    for (int j = 0; j < 4; j++) {
        float f = vv[j];
        __half h0 = __float2half_rn(f);
        float r1 = f - __half2float(h0);
        p0[j] = h0;
        p1[j] = __float2half_rn(r1 * P1_SCALE);
    }
    __half* base = g_w_cat + (size_t)o * K_CAT + k;
    *reinterpret_cast<uint2*>(base)          = *reinterpret_cast<uint2*>(p0);
    *reinterpret_cast<uint2*>(base + IN_DIM) = *reinterpret_cast<uint2*>(p1);
}

// ============================================================================
// Stage C: GEMM  C = X*W0^T + 2^-10 * (X*W1'^T)
//   CTA 128x64, 8 warps @ 64x16, BK=64, 3-stage TMA pipeline, 2 CTAs/SM.
// ============================================================================
constexpr int TILE_M = 128;
constexpr int TILE_N = 64;
constexpr int BK     = 64;
constexpr int NTH    = 256;
constexpr int KITERS = IN_DIM / BK;        // 32
constexpr int STAGES = 3;

constexpr int A_BYTES = TILE_M * BK * 2;   // 16384
constexpr int B_BYTES = TILE_N * BK * 2;   // 8192 per plane
constexpr int STAGE_BYTES = A_BYTES + 2 * B_BYTES;   // 32768
constexpr int SMEM_BYTES  = 1024 + STAGES * STAGE_BYTES;  // 99328 (x2 <= 227KB)

__global__ void __launch_bounds__(NTH, 2)
snn_gemm_kernel(const __grid_constant__ CUtensorMap tma_a,
                const __grid_constant__ CUtensorMap tma_b,
                float* __restrict__ cbuf) {
    extern __shared__ char smem_raw[];
    const uint32_t sbase = (smem_u32(smem_raw) + 1023) & ~1023u;
    const uint32_t stg_base = sbase + 1024;

    const int tid  = threadIdx.x;
    const int lane = tid & 31;
    const int wid  = tid >> 5;
    const int mw   = wid >> 2;       // 0..1 -> 64-row band
    const int nwp  = wid & 3;        // 0..3 -> 16-col band
    const int bid  = blockIdx.x;
    const int m0   = (bid >> 5) * TILE_M;   // 160 m-blocks
    const int n0   = (bid & 31) * TILE_N;   // 32 n-blocks (W stays in L2)

    if (tid == 0) {
#pragma unroll
        for (int s = 0; s < STAGES; s++) {
            MBAR_INIT(sbase + s * 8, 1);         // full: tx-based
            MBAR_INIT(sbase + 32 + s * 8, 8);    // empty: one arrive per warp
        }
    }
    __syncthreads();

    const uint64_t map_a = (uint64_t)&tma_a;
    const uint64_t map_b = (uint64_t)&tma_b;

    auto load_stage = [&](int kc) {
        const int s = kc % STAGES;
        const uint32_t stg = stg_base + s * STAGE_BYTES;
        const uint32_t mb = sbase + s * 8;
        MBAR_EXPECT_TX(mb, STAGE_BYTES);
        TMA_LOAD_2D(stg,                     map_a, kc * BK,           m0, mb);
        TMA_LOAD_2D(stg + A_BYTES,           map_b, kc * BK,           n0, mb);
        TMA_LOAD_2D(stg + A_BYTES + B_BYTES, map_b, IN_DIM + kc * BK,  n0, mb);
    };

    if (tid == 0) { load_stage(0); load_stage(1); load_stage(2); }

    const int lr = lane & 15;
    const int halfsel = (lane >> 4) * 16;
    uint32_t a_rowoff[4], a_xr[4];
#pragma unroll
    for (int mt = 0; mt < 4; mt++) {
        int r = mw * 64 + mt * 16 + lr;
        a_rowoff[mt] = r * 128;
        a_xr[mt] = (r & 7) * 16;
    }
    uint32_t b_rowoff, b_xr;
    {
        int r = nwp * 16 + lr;
        b_rowoff = r * 128;
        b_xr = (r & 7) * 16;
    }

    float acc0[4][2][4];          // [mt][n8][4] plane0 fp32
    uint32_t acc1[4][2][2];       // [mt][n8][2] plane1 fp16x2
#pragma unroll
    for (int i = 0; i < 4; i++)
#pragma unroll
        for (int j = 0; j < 2; j++) {
#pragma unroll
            for (int q = 0; q < 4; q++) acc0[i][j][q] = 0.0f;
            acc1[i][j][0] = 0u; acc1[i][j][1] = 0u;
        }

    int pf[STAGES] = {0, 0, 0}, pe[STAGES] = {0, 0, 0};

    for (int kc = 0; kc < KITERS; kc++) {
        const int s = kc % STAGES;
        const uint32_t stg = stg_base + s * STAGE_BYTES;
        MBAR_WAIT(sbase + s * 8, pf[s]);
        pf[s] ^= 1;

#pragma unroll
        for (int kk = 0; kk < 4; kk++) {
            const uint32_t kb = kk * 32 + halfsel;
            uint32_t a[4][4];
#pragma unroll
            for (int mt = 0; mt < 4; mt++)
                ldsm4(a[mt][0], a[mt][1], a[mt][2], a[mt][3],
                      stg + a_rowoff[mt] + (kb ^ a_xr[mt]));

            // ---- plane 0 (fp32 acc) ----
            {
                uint32_t b0, b1, b2, b3;
                ldsm4(b0, b1, b2, b3,
                      stg + A_BYTES + b_rowoff + (kb ^ b_xr));
#pragma unroll
                for (int mt = 0; mt < 4; mt++) {
                    mma16816(acc0[mt][0], a[mt][0], a[mt][1], a[mt][2],
                             a[mt][3], b0, b2);
                    mma16816(acc0[mt][1], a[mt][0], a[mt][1], a[mt][2],
                             a[mt][3], b1, b3);
                }
            }
            // ---- plane 1 (scaled residual, fp16 acc) ----
            {
                uint32_t b0, b1, b2, b3;
                ldsm4(b0, b1, b2, b3,
                      stg + A_BYTES + B_BYTES + b_rowoff + (kb ^ b_xr));
#pragma unroll
                for (int mt = 0; mt < 4; mt++) {
                    mma16816_h(acc1[mt][0], a[mt][0], a[mt][1], a[mt][2],
                               a[mt][3], b0, b2);
                    mma16816_h(acc1[mt][1], a[mt][0], a[mt][1], a[mt][2],
                               a[mt][3], b1, b3);
                }
            }
        }

        if (lane == 0) MBAR_ARRIVE(sbase + 32 + s * 8);
        if (tid == 0 && kc + STAGES < KITERS) {
            MBAR_WAIT(sbase + 32 + s * 8, pe[s]);
            pe[s] ^= 1;
            load_stage(kc + STAGES);
        }
    }

    // ---- epilogue: c = acc0 + acc1 * 2^-10 ----
    const int mrow = m0 + mw * 64 + (lane >> 2);
    const int ncol = n0 + nwp * 16 + (lane & 3) * 2;
#pragma unroll
    for (int mt = 0; mt < 4; mt++) {
        float* r0 = cbuf + (size_t)(mrow + mt * 16) * OUT_DIM + ncol;
        float* r1 = r0 + 8 * OUT_DIM;
#pragma unroll
        for (int j = 0; j < 2; j++) {
            float2 lo = __half22float2(
                *reinterpret_cast<const __half2*>(&acc1[mt][j][0]));
            float2 hi = __half22float2(
                *reinterpret_cast<const __half2*>(&acc1[mt][j][1]));
            *reinterpret_cast<float2*>(r0 + j * 8) =
                make_float2(fmaf(lo.x, P1_INVSCALE, acc0[mt][j][0]),
                            fmaf(lo.y, P1_INVSCALE, acc0[mt][j][1]));
            *reinterpret_cast<float2*>(r1 + j * 8) =
                make_float2(fmaf(hi.x, P1_INVSCALE, acc0[mt][j][2]),
                            fmaf(hi.y, P1_INVSCALE, acc0[mt][j][3]));
        }
    }
}

// ============================================================================
// Stage D: LIF scan over t (memory bound)
// ============================================================================
__global__ void lif_scan_kernel(const float* __restrict__ cbuf,
                                float* __restrict__ out) {
    const size_t idx4 = ((size_t)blockIdx.x * blockDim.x + threadIdx.x) * 4;
    float4 V = make_float4(0.f, 0.f, 0.f, 0.f);
    float4 I = make_float4(0.f, 0.f, 0.f, 0.f);
#pragma unroll
    for (int t = 0; t < T_STEPS; t++) {
        const size_t off = (size_t)t * BATCH * OUT_DIM + idx4;
        float4 c = *reinterpret_cast<const float4*>(cbuf + off);
        float4 s;
        I.x = ALPHA_S * I.x + c.x;  V.x = ALPHA_M * V.x + DT_TAUM * I.x;
        s.x = (V.x >= 1.0f) ? 1.0f : 0.0f;  V.x *= (1.0f - s.x);
        I.y = ALPHA_S * I.y + c.y;  V.y = ALPHA_M * V.y + DT_TAUM * I.y;
        s.y = (V.y >= 1.0f) ? 1.0f : 0.0f;  V.y *= (1.0f - s.y);
        I.z = ALPHA_S * I.z + c.z;  V.z = ALPHA_M * V.z + DT_TAUM * I.z;
        s.z = (V.z >= 1.0f) ? 1.0f : 0.0f;  V.z *= (1.0f - s.z);
        I.w = ALPHA_S * I.w + c.w;  V.w = ALPHA_M * V.w + DT_TAUM * I.w;
        s.w = (V.w >= 1.0f) ? 1.0f : 0.0f;  V.w *= (1.0f - s.w);
        *reinterpret_cast<float4*>(out + off) = s;
    }
}

}  // namespace

// ---- host-side tensormap setup (rebuilt every call; no static guards) ----
typedef CUresult (*PFN_cuTensorMapEncodeTiled)(
    CUtensorMap*, CUtensorMapDataType, cuuint32_t, void*,
    const cuuint64_t*, const cuuint64_t*, const cuuint32_t*, const cuuint32_t*,
    CUtensorMapInterleave, CUtensorMapSwizzle, CUtensorMapL2promotion,
    CUtensorMapFloatOOBfill);

static CUtensorMap s_tma_a, s_tma_b;

static void build_tensormaps() {
    PFN_cuTensorMapEncodeTiled encode = nullptr;
    cudaDriverEntryPointQueryResult qres;
    cudaGetDriverEntryPoint("cuTensorMapEncodeTiled", (void**)&encode,
                            cudaEnableDefault, &qres);
    if (!encode) return;
    void* xa; cudaGetSymbolAddress(&xa, g_x_f16);
    void* wa; cudaGetSymbolAddress(&wa, g_w_cat);

    {   // A: [2048 x 20480] fp16, box [64 x 128]
        cuuint64_t dims[2]    = {(cuuint64_t)IN_DIM, (cuuint64_t)M_TOTAL};
        cuuint64_t strides[1] = {(cuuint64_t)IN_DIM * 2};
        cuuint32_t box[2]     = {BK, TILE_M};
        cuuint32_t es[2]      = {1, 1};
        encode(&s_tma_a, CU_TENSOR_MAP_DATA_TYPE_FLOAT16, 2, xa,
               dims, strides, box, es,
               CU_TENSOR_MAP_INTERLEAVE_NONE, CU_TENSOR_MAP_SWIZZLE_128B,
               CU_TENSOR_MAP_L2_PROMOTION_L2_128B,
               CU_TENSOR_MAP_FLOAT_OOB_FILL_NONE);
    }
    {   // B: [4096 x 2048] fp16, box [64 x 64]
        cuuint64_t dims[2]    = {(cuuint64_t)K_CAT, (cuuint64_t)OUT_DIM};
        cuuint64_t strides[1] = {(cuuint64_t)K_CAT * 2};
        cuuint32_t box[2]     = {BK, TILE_N};
        cuuint32_t es[2]      = {1, 1};
        encode(&s_tma_b, CU_TENSOR_MAP_DATA_TYPE_FLOAT16, 2, wa,
               dims, strides, box, es,
               CU_TENSOR_MAP_INTERLEAVE_NONE, CU_TENSOR_MAP_SWIZZLE_128B,
               CU_TENSOR_MAP_L2_PROMOTION_L2_128B,
               CU_TENSOR_MAP_FLOAT_OOB_FILL_NONE);
    }
}

extern "C" void kernel_launch(void* const* d_in, const int* in_sizes, int n_in,
                              void* d_out, int out_size) {
    const float* x = (const float*)d_in[0];   // [T, B, IN]
    const float* w = (const float*)d_in[1];   // [OUT, IN]
    float* out = (float*)d_out;               // [T, B, OUT]

    build_tensormaps();
    float* cbuf;
    cudaGetSymbolAddress((void**)&cbuf, g_cur);

    convert_x_kernel<<<(int)((size_t)M_TOTAL * IN_DIM / 4 / 256), 256>>>(x);
    convert_w_kernel<<<(int)((size_t)OUT_DIM * IN_DIM / 4 / 256), 256>>>(w);

    cudaFuncSetAttribute(snn_gemm_kernel,
                         cudaFuncAttributeMaxDynamicSharedMemorySize, SMEM_BYTES);
    snn_gemm_kernel<<<(M_TOTAL / TILE_M) * (OUT_DIM / TILE_N), NTH, SMEM_BYTES>>>(
        s_tma_a, s_tma_b, cbuf);

    lif_scan_kernel<<<(int)((size_t)BATCH * OUT_DIM / 4 / 256), 256>>>(cbuf, out);
}

// round 11
// speedup vs baseline: 4.1036x; 1.0496x over previous
#include <cuda_runtime.h>
#include <cuda.h>
#include <cuda_fp16.h>
#include <cstdint>

// ============================================================================
// SpikingLinearLayer — fp16 2-plane GEMM (TMA, 3-stage, 256x128 tile) + LIF
//   Plane 0 (hi):       f32-accumulate HMMA
//   Plane 1 (residual): scaled 2^10, f16-accumulate HMMA, folded in epilogue
//   R11: CTA 256x128, warp 64x64 (4m x 2n), BK=64, 3-stage pipeline, 1 CTA/SM.
// ============================================================================

namespace {

constexpr int T_STEPS = 20;
constexpr int BATCH   = 1024;
constexpr int IN_DIM  = 2048;
constexpr int OUT_DIM = 2048;
constexpr int M_TOTAL = T_STEPS * BATCH;     // 20480
constexpr int K_CAT   = 2 * IN_DIM;          // 4096

constexpr float ALPHA_S = 0.8f;
constexpr float ALPHA_M = 0.95f;
constexpr float DT_TAUM = 0.05f;
constexpr float P1_SCALE    = 1024.0f;
constexpr float P1_INVSCALE = 0.0009765625f;   // 2^-10

__device__ __align__(1024) __half g_x_f16[(size_t)M_TOTAL * IN_DIM];   // 84 MB
__device__ __align__(1024) __half g_w_cat[(size_t)OUT_DIM * K_CAT];    // 17 MB
__device__ __align__(1024) float  g_cur[(size_t)M_TOTAL * OUT_DIM];    // 168 MB

__device__ __forceinline__ uint32_t smem_u32(const void* p) {
    uint32_t a;
    asm("{ .reg .u64 t; cvta.to.shared.u64 t, %1; cvt.u32.u64 %0, t; }"
        : "=r"(a) : "l"(p));
    return a;
}

#define MBAR_INIT(addr, cnt) \
    asm volatile("mbarrier.init.shared.b64 [%0], %1;" :: "r"(addr), "r"(cnt) : "memory")
#define MBAR_ARRIVE(addr) \
    asm volatile("mbarrier.arrive.shared.b64 _, [%0];" :: "r"(addr) : "memory")
#define MBAR_EXPECT_TX(addr, bytes) \
    asm volatile("mbarrier.arrive.expect_tx.shared.b64 _, [%0], %1;" \
        :: "r"(addr), "r"(bytes) : "memory")
#define MBAR_WAIT(addr, ph) do {                                                   \
    uint32_t _m = (addr), _p = (ph), _d;                                           \
    asm volatile("{\n\t.reg .pred p;\n\t"                                          \
        "mbarrier.try_wait.parity.acquire.cta.shared::cta.b64 p, [%1], %2;\n\t"    \
        "selp.b32 %0, 1, 0, p;\n\t}" : "=r"(_d) : "r"(_m), "r"(_p) : "memory");    \
    if (!_d) {                                                                     \
        asm volatile("{\n\t.reg .pred P;\n\t"                                      \
        "WL_%=:\n\t"                                                               \
        "mbarrier.try_wait.parity.acquire.cta.shared::cta.b64 P, [%0], %1, 0x989680;\n\t" \
        "@P bra.uni WD_%=;\n\t"                                                    \
        "bra.uni WL_%=;\n\t"                                                       \
        "WD_%=:\n\t}" :: "r"(_m), "r"(_p) : "memory");                             \
    }                                                                              \
} while (0)

#define TMA_LOAD_2D(dst, map_addr, c0, c1, mbar) \
    asm volatile( \
        "cp.async.bulk.tensor.2d.shared::cta.global.tile.mbarrier::complete_tx::bytes " \
        "[%0], [%1, {%2, %3}], [%4];" \
        :: "r"(dst), "l"(map_addr), "r"(c0), "r"(c1), "r"(mbar) : "memory")

__device__ __forceinline__ void ldsm4(uint32_t& r0, uint32_t& r1, uint32_t& r2,
                                      uint32_t& r3, uint32_t addr) {
    asm volatile("ldmatrix.sync.aligned.m8n8.x4.shared.b16 {%0,%1,%2,%3}, [%4];"
                 : "=r"(r0), "=r"(r1), "=r"(r2), "=r"(r3) : "r"(addr));
}

__device__ __forceinline__ void mma16816(float* d, uint32_t a0, uint32_t a1,
                                         uint32_t a2, uint32_t a3,
                                         uint32_t b0, uint32_t b1) {
    asm volatile(
        "mma.sync.aligned.m16n8k16.row.col.f32.f16.f16.f32 "
        "{%0,%1,%2,%3}, {%4,%5,%6,%7}, {%8,%9}, {%0,%1,%2,%3};"
        : "+f"(d[0]), "+f"(d[1]), "+f"(d[2]), "+f"(d[3])
        : "r"(a0), "r"(a1), "r"(a2), "r"(a3), "r"(b0), "r"(b1));
}

__device__ __forceinline__ void mma16816_h(uint32_t* d, uint32_t a0, uint32_t a1,
                                           uint32_t a2, uint32_t a3,
                                           uint32_t b0, uint32_t b1) {
    asm volatile(
        "mma.sync.aligned.m16n8k16.row.col.f16.f16.f16.f16 "
        "{%0,%1}, {%2,%3,%4,%5}, {%6,%7}, {%0,%1};"
        : "+r"(d[0]), "+r"(d[1])
        : "r"(a0), "r"(a1), "r"(a2), "r"(a3), "r"(b0), "r"(b1));
}

// ============================================================================
// Stage A: x fp32 -> fp16  (binary values: exact)
// ============================================================================
__global__ void convert_x_kernel(const float* __restrict__ x) {
    size_t i = ((size_t)blockIdx.x * blockDim.x + threadIdx.x) * 4;
    float4 v = *reinterpret_cast<const float4*>(x + i);
    __half2 lo = __floats2half2_rn(v.x, v.y);
    __half2 hi = __floats2half2_rn(v.z, v.w);
    uint2 packed = make_uint2(*reinterpret_cast<uint32_t*>(&lo),
                              *reinterpret_cast<uint32_t*>(&hi));
    *reinterpret_cast<uint2*>(g_x_f16 + i) = packed;
}

// ============================================================================
// Stage B: w -> plane0 fp16(w), plane1 fp16(1024*(w - plane0)); concat on K
// ============================================================================
__global__ void convert_w_kernel(const float* __restrict__ w) {
    size_t i = ((size_t)blockIdx.x * blockDim.x + threadIdx.x) * 4;
    int o = (int)(i / IN_DIM);
    int k = (int)(i % IN_DIM);
    float4 v = *reinterpret_cast<const float4*>(w + i);
    float vv[4] = {v.x, v.y, v.z, v.w};
    __half p0[4], p1[4];
#pragma unroll
    for (int j = 0; j < 4; j++) {
        float f = vv[j];
        __half h0 = __float2half_rn(f);
        float r1 = f - __half2float(h0);
        p0[j] = h0;
        p1[j] = __float2half_rn(r1 * P1_SCALE);
    }
    __half* base = g_w_cat + (size_t)o * K_CAT + k;
    *reinterpret_cast<uint2*>(base)          = *reinterpret_cast<uint2*>(p0);
    *reinterpret_cast<uint2*>(base + IN_DIM) = *reinterpret_cast<uint2*>(p1);
}

// ============================================================================
// Stage C: GEMM  C = X*W0^T + 2^-10 * (X*W1'^T)
//   CTA 256x128, 8 warps @ 64x64 (4m x 2n), BK=64, 3-stage TMA pipeline.
// ============================================================================
constexpr int TILE_M = 256;
constexpr int TILE_N = 128;
constexpr int BK     = 64;
constexpr int NTH    = 256;
constexpr int KITERS = IN_DIM / BK;        // 32
constexpr int STAGES = 3;

constexpr int A_BYTES = TILE_M * BK * 2;   // 32768
constexpr int B_BYTES = TILE_N * BK * 2;   // 16384 per plane
constexpr int STAGE_BYTES = A_BYTES + 2 * B_BYTES;       // 65536
constexpr int SMEM_BYTES  = 1024 + STAGES * STAGE_BYTES; // 197632

__global__ void __launch_bounds__(NTH, 1)
snn_gemm_kernel(const __grid_constant__ CUtensorMap tma_a,
                const __grid_constant__ CUtensorMap tma_b,
                float* __restrict__ cbuf) {
    extern __shared__ char smem_raw[];
    const uint32_t sbase = (smem_u32(smem_raw) + 1023) & ~1023u;
    const uint32_t stg_base = sbase + 1024;

    const int tid  = threadIdx.x;
    const int lane = tid & 31;
    const int wid  = tid >> 5;
    const int mw   = wid >> 1;       // 0..3 -> 64-row band (256 M)
    const int nw   = wid & 1;        // 0..1 -> 64-col band (128 N)
    const int bid  = blockIdx.x;
    const int m0   = (bid >> 4) * TILE_M;   // 80 m-blocks
    const int n0   = (bid & 15) * TILE_N;   // 16 n-blocks (W stays in L2)

    if (tid == 0) {
#pragma unroll
        for (int s = 0; s < STAGES; s++) {
            MBAR_INIT(sbase + s * 8, 1);         // full: tx-based
            MBAR_INIT(sbase + 32 + s * 8, 8);    // empty: one arrive per warp
        }
    }
    __syncthreads();

    const uint64_t map_a = (uint64_t)&tma_a;
    const uint64_t map_b = (uint64_t)&tma_b;

    auto load_stage = [&](int kc) {
        const int s = kc % STAGES;
        const uint32_t stg = stg_base + s * STAGE_BYTES;
        const uint32_t mb = sbase + s * 8;
        MBAR_EXPECT_TX(mb, STAGE_BYTES);
        TMA_LOAD_2D(stg,                     map_a, kc * BK,           m0, mb);
        TMA_LOAD_2D(stg + A_BYTES,           map_b, kc * BK,           n0, mb);
        TMA_LOAD_2D(stg + A_BYTES + B_BYTES, map_b, IN_DIM + kc * BK,  n0, mb);
    };

    if (tid == 0) { load_stage(0); load_stage(1); load_stage(2); }

    const int lr = lane & 15;
    const int halfsel = (lane >> 4) * 16;
    uint32_t a_rowoff[4], a_xr[4];
#pragma unroll
    for (int mt = 0; mt < 4; mt++) {
        int r = mw * 64 + mt * 16 + lr;       // 0..255
        a_rowoff[mt] = r * 128;
        a_xr[mt] = (r & 7) * 16;
    }
    uint32_t b_rowoff[4], b_xr[4];
#pragma unroll
    for (int nt = 0; nt < 4; nt++) {
        int r = nw * 64 + nt * 16 + lr;       // 0..127
        b_rowoff[nt] = r * 128;
        b_xr[nt] = (r & 7) * 16;
    }

    float acc0[4][8][4];          // [mt][n8][4] plane0 fp32
    uint32_t acc1[4][8][2];       // [mt][n8][2] plane1 fp16x2
#pragma unroll
    for (int i = 0; i < 4; i++)
#pragma unroll
        for (int j = 0; j < 8; j++) {
#pragma unroll
            for (int q = 0; q < 4; q++) acc0[i][j][q] = 0.0f;
            acc1[i][j][0] = 0u; acc1[i][j][1] = 0u;
        }

    int pf[STAGES] = {0, 0, 0}, pe[STAGES] = {0, 0, 0};

    for (int kc = 0; kc < KITERS; kc++) {
        const int s = kc % STAGES;
        const uint32_t stg = stg_base + s * STAGE_BYTES;
        MBAR_WAIT(sbase + s * 8, pf[s]);
        pf[s] ^= 1;

#pragma unroll
        for (int kk = 0; kk < 4; kk++) {
            const uint32_t kb = kk * 32 + halfsel;
            uint32_t a[4][4];
#pragma unroll
            for (int mt = 0; mt < 4; mt++)
                ldsm4(a[mt][0], a[mt][1], a[mt][2], a[mt][3],
                      stg + a_rowoff[mt] + (kb ^ a_xr[mt]));

            // ---- plane 0 (fp32 acc) ----
#pragma unroll
            for (int nt = 0; nt < 4; nt++) {
                uint32_t b0, b1, b2, b3;
                ldsm4(b0, b1, b2, b3,
                      stg + A_BYTES + b_rowoff[nt] + (kb ^ b_xr[nt]));
#pragma unroll
                for (int mt = 0; mt < 4; mt++) {
                    mma16816(acc0[mt][nt * 2 + 0], a[mt][0], a[mt][1],
                             a[mt][2], a[mt][3], b0, b2);
                    mma16816(acc0[mt][nt * 2 + 1], a[mt][0], a[mt][1],
                             a[mt][2], a[mt][3], b1, b3);
                }
            }
            // ---- plane 1 (scaled residual, fp16 acc) ----
#pragma unroll
            for (int nt = 0; nt < 4; nt++) {
                uint32_t b0, b1, b2, b3;
                ldsm4(b0, b1, b2, b3,
                      stg + A_BYTES + B_BYTES + b_rowoff[nt] + (kb ^ b_xr[nt]));
#pragma unroll
                for (int mt = 0; mt < 4; mt++) {
                    mma16816_h(acc1[mt][nt * 2 + 0], a[mt][0], a[mt][1],
                               a[mt][2], a[mt][3], b0, b2);
                    mma16816_h(acc1[mt][nt * 2 + 1], a[mt][0], a[mt][1],
                               a[mt][2], a[mt][3], b1, b3);
                }
            }
        }

        if (lane == 0) MBAR_ARRIVE(sbase + 32 + s * 8);
        if (tid == 0 && kc + STAGES < KITERS) {
            MBAR_WAIT(sbase + 32 + s * 8, pe[s]);
            pe[s] ^= 1;
            load_stage(kc + STAGES);
        }
    }

    // ---- epilogue: c = acc0 + acc1 * 2^-10 ----
    const int mrow = m0 + mw * 64 + (lane >> 2);
    const int ncol = n0 + nw * 64 + (lane & 3) * 2;
#pragma unroll
    for (int mt = 0; mt < 4; mt++) {
        float* r0 = cbuf + (size_t)(mrow + mt * 16) * OUT_DIM + ncol;
        float* r1 = r0 + 8 * OUT_DIM;
#pragma unroll
        for (int j = 0; j < 8; j++) {
            float2 lo = __half22float2(
                *reinterpret_cast<const __half2*>(&acc1[mt][j][0]));
            float2 hi = __half22float2(
                *reinterpret_cast<const __half2*>(&acc1[mt][j][1]));
            *reinterpret_cast<float2*>(r0 + j * 8) =
                make_float2(fmaf(lo.x, P1_INVSCALE, acc0[mt][j][0]),
                            fmaf(lo.y, P1_INVSCALE, acc0[mt][j][1]));
            *reinterpret_cast<float2*>(r1 + j * 8) =
                make_float2(fmaf(hi.x, P1_INVSCALE, acc0[mt][j][2]),
                            fmaf(hi.y, P1_INVSCALE, acc0[mt][j][3]));
        }
    }
}

// ============================================================================
// Stage D: LIF scan over t (memory bound)
// ============================================================================
__global__ void lif_scan_kernel(const float* __restrict__ cbuf,
                                float* __restrict__ out) {
    const size_t idx4 = ((size_t)blockIdx.x * blockDim.x + threadIdx.x) * 4;
    float4 V = make_float4(0.f, 0.f, 0.f, 0.f);
    float4 I = make_float4(0.f, 0.f, 0.f, 0.f);
#pragma unroll
    for (int t = 0; t < T_STEPS; t++) {
        const size_t off = (size_t)t * BATCH * OUT_DIM + idx4;
        float4 c = *reinterpret_cast<const float4*>(cbuf + off);
        float4 s;
        I.x = ALPHA_S * I.x + c.x;  V.x = ALPHA_M * V.x + DT_TAUM * I.x;
        s.x = (V.x >= 1.0f) ? 1.0f : 0.0f;  V.x *= (1.0f - s.x);
        I.y = ALPHA_S * I.y + c.y;  V.y = ALPHA_M * V.y + DT_TAUM * I.y;
        s.y = (V.y >= 1.0f) ? 1.0f : 0.0f;  V.y *= (1.0f - s.y);
        I.z = ALPHA_S * I.z + c.z;  V.z = ALPHA_M * V.z + DT_TAUM * I.z;
        s.z = (V.z >= 1.0f) ? 1.0f : 0.0f;  V.z *= (1.0f - s.z);
        I.w = ALPHA_S * I.w + c.w;  V.w = ALPHA_M * V.w + DT_TAUM * I.w;
        s.w = (V.w >= 1.0f) ? 1.0f : 0.0f;  V.w *= (1.0f - s.w);
        *reinterpret_cast<float4*>(out + off) = s;
    }
}

}  // namespace

// ---- host-side tensormap setup (rebuilt every call; no static guards) ----
typedef CUresult (*PFN_cuTensorMapEncodeTiled)(
    CUtensorMap*, CUtensorMapDataType, cuuint32_t, void*,
    const cuuint64_t*, const cuuint64_t*, const cuuint32_t*, const cuuint32_t*,
    CUtensorMapInterleave, CUtensorMapSwizzle, CUtensorMapL2promotion,
    CUtensorMapFloatOOBfill);

static CUtensorMap s_tma_a, s_tma_b;

static void build_tensormaps() {
    PFN_cuTensorMapEncodeTiled encode = nullptr;
    cudaDriverEntryPointQueryResult qres;
    cudaGetDriverEntryPoint("cuTensorMapEncodeTiled", (void**)&encode,
                            cudaEnableDefault, &qres);
    if (!encode) return;
    void* xa; cudaGetSymbolAddress(&xa, g_x_f16);
    void* wa; cudaGetSymbolAddress(&wa, g_w_cat);

    {   // A: [2048 x 20480] fp16, box [64 x 256]
        cuuint64_t dims[2]    = {(cuuint64_t)IN_DIM, (cuuint64_t)M_TOTAL};
        cuuint64_t strides[1] = {(cuuint64_t)IN_DIM * 2};
        cuuint32_t box[2]     = {BK, TILE_M};
        cuuint32_t es[2]      = {1, 1};
        encode(&s_tma_a, CU_TENSOR_MAP_DATA_TYPE_FLOAT16, 2, xa,
               dims, strides, box, es,
               CU_TENSOR_MAP_INTERLEAVE_NONE, CU_TENSOR_MAP_SWIZZLE_128B,
               CU_TENSOR_MAP_L2_PROMOTION_L2_128B,
               CU_TENSOR_MAP_FLOAT_OOB_FILL_NONE);
    }
    {   // B: [4096 x 2048] fp16, box [64 x 128]
        cuuint64_t dims[2]    = {(cuuint64_t)K_CAT, (cuuint64_t)OUT_DIM};
        cuuint64_t strides[1] = {(cuuint64_t)K_CAT * 2};
        cuuint32_t box[2]     = {BK, TILE_N};
        cuuint32_t es[2]      = {1, 1};
        encode(&s_tma_b, CU_TENSOR_MAP_DATA_TYPE_FLOAT16, 2, wa,
               dims, strides, box, es,
               CU_TENSOR_MAP_INTERLEAVE_NONE, CU_TENSOR_MAP_SWIZZLE_128B,
               CU_TENSOR_MAP_L2_PROMOTION_L2_128B,
               CU_TENSOR_MAP_FLOAT_OOB_FILL_NONE);
    }
}

extern "C" void kernel_launch(void* const* d_in, const int* in_sizes, int n_in,
                              void* d_out, int out_size) {
    const float* x = (const float*)d_in[0];   // [T, B, IN]
    const float* w = (const float*)d_in[1];   // [OUT, IN]
    float* out = (float*)d_out;               // [T, B, OUT]

    build_tensormaps();
    float* cbuf;
    cudaGetSymbolAddress((void**)&cbuf, g_cur);

    convert_x_kernel<<<(int)((size_t)M_TOTAL * IN_DIM / 4 / 256), 256>>>(x);
    convert_w_kernel<<<(int)((size_t)OUT_DIM * IN_DIM / 4 / 256), 256>>>(w);

    cudaFuncSetAttribute(snn_gemm_kernel,
                         cudaFuncAttributeMaxDynamicSharedMemorySize, SMEM_BYTES);
    snn_gemm_kernel<<<(M_TOTAL / TILE_M) * (OUT_DIM / TILE_N), NTH, SMEM_BYTES>>>(
        s_tma_a, s_tma_b, cbuf);

    lif_scan_kernel<<<(int)((size_t)BATCH * OUT_DIM / 4 / 256), 256>>>(cbuf, out);
}

// round 15
// speedup vs baseline: 4.1536x; 1.0122x over previous
#include <cuda_runtime.h>
#include <cuda.h>
#include <cuda_fp16.h>
#include <cstdint>

// ============================================================================
// SpikingLinearLayer — fp16 2-plane GEMM (R6 core, best known) + LIF scan
//   Plane 0 (hi):       f32-accumulate HMMA
//   Plane 1 (residual): scaled 2^10, f16-accumulate HMMA, folded in epilogue
//   R14: R6 GEMM verbatim; merged converts; cache-hinted LIF scan.
// ============================================================================

namespace {

constexpr int T_STEPS = 20;
constexpr int BATCH   = 1024;
constexpr int IN_DIM  = 2048;
constexpr int OUT_DIM = 2048;
constexpr int M_TOTAL = T_STEPS * BATCH;     // 20480
constexpr int K_CAT   = 2 * IN_DIM;          // 4096

constexpr float ALPHA_S = 0.8f;
constexpr float ALPHA_M = 0.95f;
constexpr float DT_TAUM = 0.05f;
constexpr float P1_SCALE    = 1024.0f;
constexpr float P1_INVSCALE = 0.0009765625f;   // 2^-10

__device__ __align__(1024) __half g_x_f16[(size_t)M_TOTAL * IN_DIM];   // 84 MB
__device__ __align__(1024) __half g_w_cat[(size_t)OUT_DIM * K_CAT];    // 17 MB
__device__ __align__(1024) float  g_cur[(size_t)M_TOTAL * OUT_DIM];    // 168 MB

__device__ __forceinline__ uint32_t smem_u32(const void* p) {
    uint32_t a;
    asm("{ .reg .u64 t; cvta.to.shared.u64 t, %1; cvt.u32.u64 %0, t; }"
        : "=r"(a) : "l"(p));
    return a;
}

#define MBAR_INIT(addr, cnt) \
    asm volatile("mbarrier.init.shared.b64 [%0], %1;" :: "r"(addr), "r"(cnt) : "memory")
#define MBAR_ARRIVE(addr) \
    asm volatile("mbarrier.arrive.shared.b64 _, [%0];" :: "r"(addr) : "memory")
#define MBAR_EXPECT_TX(addr, bytes) \
    asm volatile("mbarrier.arrive.expect_tx.shared.b64 _, [%0], %1;" \
        :: "r"(addr), "r"(bytes) : "memory")
#define MBAR_WAIT(addr, ph) do {                                                   \
    uint32_t _m = (addr), _p = (ph), _d;                                           \
    asm volatile("{\n\t.reg .pred p;\n\t"                                          \
        "mbarrier.try_wait.parity.acquire.cta.shared::cta.b64 p, [%1], %2;\n\t"    \
        "selp.b32 %0, 1, 0, p;\n\t}" : "=r"(_d) : "r"(_m), "r"(_p) : "memory");    \
    if (!_d) {                                                                     \
        asm volatile("{\n\t.reg .pred P;\n\t"                                      \
        "WL_%=:\n\t"                                                               \
        "mbarrier.try_wait.parity.acquire.cta.shared::cta.b64 P, [%0], %1, 0x989680;\n\t" \
        "@P bra.uni WD_%=;\n\t"                                                    \
        "bra.uni WL_%=;\n\t"                                                       \
        "WD_%=:\n\t}" :: "r"(_m), "r"(_p) : "memory");                             \
    }                                                                              \
} while (0)

#define TMA_LOAD_2D(dst, map_addr, c0, c1, mbar) \
    asm volatile( \
        "cp.async.bulk.tensor.2d.shared::cta.global.tile.mbarrier::complete_tx::bytes " \
        "[%0], [%1, {%2, %3}], [%4];" \
        :: "r"(dst), "l"(map_addr), "r"(c0), "r"(c1), "r"(mbar) : "memory")

__device__ __forceinline__ void ldsm4(uint32_t& r0, uint32_t& r1, uint32_t& r2,
                                      uint32_t& r3, uint32_t addr) {
    asm volatile("ldmatrix.sync.aligned.m8n8.x4.shared.b16 {%0,%1,%2,%3}, [%4];"
                 : "=r"(r0), "=r"(r1), "=r"(r2), "=r"(r3) : "r"(addr));
}

__device__ __forceinline__ void mma16816(float* d, uint32_t a0, uint32_t a1,
                                         uint32_t a2, uint32_t a3,
                                         uint32_t b0, uint32_t b1) {
    asm volatile(
        "mma.sync.aligned.m16n8k16.row.col.f32.f16.f16.f32 "
        "{%0,%1,%2,%3}, {%4,%5,%6,%7}, {%8,%9}, {%0,%1,%2,%3};"
        : "+f"(d[0]), "+f"(d[1]), "+f"(d[2]), "+f"(d[3])
        : "r"(a0), "r"(a1), "r"(a2), "r"(a3), "r"(b0), "r"(b1));
}

__device__ __forceinline__ void mma16816_h(uint32_t* d, uint32_t a0, uint32_t a1,
                                           uint32_t a2, uint32_t a3,
                                           uint32_t b0, uint32_t b1) {
    asm volatile(
        "mma.sync.aligned.m16n8k16.row.col.f16.f16.f16.f16 "
        "{%0,%1}, {%2,%3,%4,%5}, {%6,%7}, {%0,%1};"
        : "+r"(d[0]), "+r"(d[1])
        : "r"(a0), "r"(a1), "r"(a2), "r"(a3), "r"(b0), "r"(b1));
}

// ============================================================================
// Merged converts: x fp32 -> fp16 ; w -> 2 fp16 planes (hi + scaled residual)
// ============================================================================
constexpr int XBLKS = (int)((size_t)M_TOTAL * IN_DIM / 4 / 256);  // 40960
constexpr int WBLKS = (int)((size_t)OUT_DIM * IN_DIM / 4 / 256);  // 4096

__global__ void convert_all_kernel(const float* __restrict__ x,
                                   const float* __restrict__ w) {
    const int bid = blockIdx.x;
    if (bid < XBLKS) {
        size_t i = ((size_t)bid * blockDim.x + threadIdx.x) * 4;
        float4 v = *reinterpret_cast<const float4*>(x + i);
        __half2 lo = __floats2half2_rn(v.x, v.y);
        __half2 hi = __floats2half2_rn(v.z, v.w);
        uint2 packed = make_uint2(*reinterpret_cast<uint32_t*>(&lo),
                                  *reinterpret_cast<uint32_t*>(&hi));
        *reinterpret_cast<uint2*>(g_x_f16 + i) = packed;
    } else {
        size_t i = ((size_t)(bid - XBLKS) * blockDim.x + threadIdx.x) * 4;
        int o = (int)(i / IN_DIM);
        int k = (int)(i % IN_DIM);
        float4 v = *reinterpret_cast<const float4*>(w + i);
        float vv[4] = {v.x, v.y, v.z, v.w};
        __half p0[4], p1[4];
#pragma unroll
        for (int j = 0; j < 4; j++) {
            float f = vv[j];
            __half h0 = __float2half_rn(f);
            float r1 = f - __half2float(h0);
            p0[j] = h0;
            p1[j] = __float2half_rn(r1 * P1_SCALE);
        }
        __half* base = g_w_cat + (size_t)o * K_CAT + k;
        *reinterpret_cast<uint2*>(base)          = *reinterpret_cast<uint2*>(p0);
        *reinterpret_cast<uint2*>(base + IN_DIM) = *reinterpret_cast<uint2*>(p1);
    }
}

// ============================================================================
// GEMM  C = X*W0^T + 2^-10 * (X*W1'^T)   (R6 core, verbatim)
//   CTA 128x256, 8 warps @ 64x64, BK=64, 2-stage TMA pipeline.
// ============================================================================
constexpr int TILE_M = 128;
constexpr int TILE_N = 256;
constexpr int BK     = 64;
constexpr int NTH    = 256;
constexpr int KITERS = IN_DIM / BK;        // 32

constexpr int A_BYTES  = TILE_M * BK * 2;  // 16384
constexpr int B_BYTES  = TILE_N * BK * 2;  // 32768 per plane
constexpr int STAGE_BYTES = A_BYTES + 2 * B_BYTES;  // 81920
constexpr int SMEM_BYTES  = 2048 + 2 * STAGE_BYTES;

__global__ void __launch_bounds__(NTH, 1)
snn_gemm_kernel(const __grid_constant__ CUtensorMap tma_a,
                const __grid_constant__ CUtensorMap tma_b,
                float* __restrict__ cbuf) {
    extern __shared__ char smem_raw[];
    const uint32_t sbase = (smem_u32(smem_raw) + 1023) & ~1023u;
    const uint32_t stg_base = sbase + 1024;

    const int tid  = threadIdx.x;
    const int lane = tid & 31;
    const int wid  = tid >> 5;
    const int mw   = wid & 1;
    const int nw   = wid >> 1;
    const int bid  = blockIdx.x;
    const int m0   = (bid >> 3) * TILE_M;   // 160 m-blocks
    const int n0   = (bid & 7) * TILE_N;    // 8 n-blocks (wave shares W in L2)

    if (tid == 0) {
#pragma unroll
        for (int s = 0; s < 2; s++) {
            MBAR_INIT(sbase + s * 8, 1);         // full: tx-based
            MBAR_INIT(sbase + 16 + s * 8, NTH);  // empty: all threads arrive
        }
    }
    __syncthreads();

    const uint64_t map_a = (uint64_t)&tma_a;
    const uint64_t map_b = (uint64_t)&tma_b;

    auto load_stage = [&](int kc) {
        const int s = kc & 1;
        const uint32_t stg = stg_base + s * STAGE_BYTES;
        const uint32_t mb = sbase + s * 8;
        MBAR_EXPECT_TX(mb, STAGE_BYTES);
        TMA_LOAD_2D(stg,                     map_a, kc * BK,           m0, mb);
        TMA_LOAD_2D(stg + A_BYTES,           map_b, kc * BK,           n0, mb);
        TMA_LOAD_2D(stg + A_BYTES + B_BYTES, map_b, IN_DIM + kc * BK,  n0, mb);
    };

    if (tid == 0) { load_stage(0); load_stage(1); }

    const int lr = lane & 15;
    const int halfsel = (lane >> 4) * 16;
    uint32_t a_rowoff[4], a_xr[4];
#pragma unroll
    for (int mt = 0; mt < 4; mt++) {
        int r = mw * 64 + mt * 16 + lr;
        a_rowoff[mt] = r * 128;
        a_xr[mt] = (r & 7) * 16;
    }
    uint32_t b_rowoff[4], b_xr[4];
#pragma unroll
    for (int nt = 0; nt < 4; nt++) {
        int r = nw * 64 + nt * 16 + lr;
        b_rowoff[nt] = r * 128;
        b_xr[nt] = (r & 7) * 16;
    }

    float acc0[4][8][4];          // [mt][n8][4] plane0 fp32
    uint32_t acc1[4][8][2];       // [mt][n8][2] plane1 fp16x2
#pragma unroll
    for (int i = 0; i < 4; i++)
#pragma unroll
        for (int j = 0; j < 8; j++) {
#pragma unroll
            for (int q = 0; q < 4; q++) acc0[i][j][q] = 0.0f;
            acc1[i][j][0] = 0u; acc1[i][j][1] = 0u;
        }

    int pf[2] = {0, 0}, pe[2] = {0, 0};

    for (int kc = 0; kc < KITERS; kc++) {
        const int s = kc & 1;
        const uint32_t stg = stg_base + s * STAGE_BYTES;
        MBAR_WAIT(sbase + s * 8, pf[s]);
        pf[s] ^= 1;

#pragma unroll
        for (int kk = 0; kk < 4; kk++) {
            const uint32_t kb = kk * 32 + halfsel;
            uint32_t a[4][4];
#pragma unroll
            for (int mt = 0; mt < 4; mt++)
                ldsm4(a[mt][0], a[mt][1], a[mt][2], a[mt][3],
                      stg + a_rowoff[mt] + (kb ^ a_xr[mt]));

            // ---- plane 0 (fp32 acc) ----
#pragma unroll
            for (int nt = 0; nt < 4; nt++) {
                uint32_t b0, b1, b2, b3;
                ldsm4(b0, b1, b2, b3,
                      stg + A_BYTES + b_rowoff[nt] + (kb ^ b_xr[nt]));
#pragma unroll
                for (int mt = 0; mt < 4; mt++) {
                    mma16816(acc0[mt][nt * 2 + 0], a[mt][0], a[mt][1],
                             a[mt][2], a[mt][3], b0, b2);
                    mma16816(acc0[mt][nt * 2 + 1], a[mt][0], a[mt][1],
                             a[mt][2], a[mt][3], b1, b3);
                }
            }
            // ---- plane 1 (scaled residual, fp16 acc) ----
#pragma unroll
            for (int nt = 0; nt < 4; nt++) {
                uint32_t b0, b1, b2, b3;
                ldsm4(b0, b1, b2, b3,
                      stg + A_BYTES + B_BYTES + b_rowoff[nt] + (kb ^ b_xr[nt]));
#pragma unroll
                for (int mt = 0; mt < 4; mt++) {
                    mma16816_h(acc1[mt][nt * 2 + 0], a[mt][0], a[mt][1],
                               a[mt][2], a[mt][3], b0, b2);
                    mma16816_h(acc1[mt][nt * 2 + 1], a[mt][0], a[mt][1],
                               a[mt][2], a[mt][3], b1, b3);
                }
            }
        }

        MBAR_ARRIVE(sbase + 16 + s * 8);
        if (tid == 0 && kc + 2 < KITERS) {
            MBAR_WAIT(sbase + 16 + s * 8, pe[s]);
            pe[s] ^= 1;
            load_stage(kc + 2);
        }
    }

    // ---- epilogue: c = acc0 + acc1 * 2^-10 ----
    const int mrow = m0 + mw * 64 + (lane >> 2);
    const int ncol = n0 + nw * 64 + (lane & 3) * 2;
#pragma unroll
    for (int mt = 0; mt < 4; mt++) {
        float* r0 = cbuf + (size_t)(mrow + mt * 16) * OUT_DIM + ncol;
        float* r1 = r0 + 8 * OUT_DIM;
#pragma unroll
        for (int j = 0; j < 8; j++) {
            float2 lo = __half22float2(
                *reinterpret_cast<const __half2*>(&acc1[mt][j][0]));
            float2 hi = __half22float2(
                *reinterpret_cast<const __half2*>(&acc1[mt][j][1]));
            *reinterpret_cast<float2*>(r0 + j * 8) =
                make_float2(fmaf(lo.x, P1_INVSCALE, acc0[mt][j][0]),
                            fmaf(lo.y, P1_INVSCALE, acc0[mt][j][1]));
            *reinterpret_cast<float2*>(r1 + j * 8) =
                make_float2(fmaf(hi.x, P1_INVSCALE, acc0[mt][j][2]),
                            fmaf(hi.y, P1_INVSCALE, acc0[mt][j][3]));
        }
    }
}

// ============================================================================
// LIF scan over t (memory bound; read-once/write-once cache hints)
// ============================================================================
__global__ void lif_scan_kernel(const float* __restrict__ cbuf,
                                float* __restrict__ out) {
    const size_t idx4 = ((size_t)blockIdx.x * blockDim.x + threadIdx.x) * 4;
    float4 V = make_float4(0.f, 0.f, 0.f, 0.f);
    float4 I = make_float4(0.f, 0.f, 0.f, 0.f);
#pragma unroll
    for (int t = 0; t < T_STEPS; t++) {
        const size_t off = (size_t)t * BATCH * OUT_DIM + idx4;
        float4 c = __ldcs(reinterpret_cast<const float4*>(cbuf + off));
        float4 s;
        I.x = ALPHA_S * I.x + c.x;  V.x = ALPHA_M * V.x + DT_TAUM * I.x;
        s.x = (V.x >= 1.0f) ? 1.0f : 0.0f;  V.x *= (1.0f - s.x);
        I.y = ALPHA_S * I.y + c.y;  V.y = ALPHA_M * V.y + DT_TAUM * I.y;
        s.y = (V.y >= 1.0f) ? 1.0f : 0.0f;  V.y *= (1.0f - s.y);
        I.z = ALPHA_S * I.z + c.z;  V.z = ALPHA_M * V.z + DT_TAUM * I.z;
        s.z = (V.z >= 1.0f) ? 1.0f : 0.0f;  V.z *= (1.0f - s.z);
        I.w = ALPHA_S * I.w + c.w;  V.w = ALPHA_M * V.w + DT_TAUM * I.w;
        s.w = (V.w >= 1.0f) ? 1.0f : 0.0f;  V.w *= (1.0f - s.w);
        __stcs(reinterpret_cast<float4*>(out + off), s);
    }
}

}  // namespace

// ---- host-side tensormap setup (rebuilt every call; no static guards) ----
typedef CUresult (*PFN_cuTensorMapEncodeTiled)(
    CUtensorMap*, CUtensorMapDataType, cuuint32_t, void*,
    const cuuint64_t*, const cuuint64_t*, const cuuint32_t*, const cuuint32_t*,
    CUtensorMapInterleave, CUtensorMapSwizzle, CUtensorMapL2promotion,
    CUtensorMapFloatOOBfill);

static CUtensorMap s_tma_a, s_tma_b;

static void build_tensormaps() {
    PFN_cuTensorMapEncodeTiled encode = nullptr;
    cudaDriverEntryPointQueryResult qres;
    cudaGetDriverEntryPoint("cuTensorMapEncodeTiled", (void**)&encode,
                            cudaEnableDefault, &qres);
    if (!encode) return;
    void* xa; cudaGetSymbolAddress(&xa, g_x_f16);
    void* wa; cudaGetSymbolAddress(&wa, g_w_cat);

    {   // A: [2048 x 20480] fp16, box [64 x 128]
        cuuint64_t dims[2]    = {(cuuint64_t)IN_DIM, (cuuint64_t)M_TOTAL};
        cuuint64_t strides[1] = {(cuuint64_t)IN_DIM * 2};
        cuuint32_t box[2]     = {BK, TILE_M};
        cuuint32_t es[2]      = {1, 1};
        encode(&s_tma_a, CU_TENSOR_MAP_DATA_TYPE_FLOAT16, 2, xa,
               dims, strides, box, es,
               CU_TENSOR_MAP_INTERLEAVE_NONE, CU_TENSOR_MAP_SWIZZLE_128B,
               CU_TENSOR_MAP_L2_PROMOTION_L2_128B,
               CU_TENSOR_MAP_FLOAT_OOB_FILL_NONE);
    }
    {   // B: [4096 x 2048] fp16, box [64 x 256]
        cuuint64_t dims[2]    = {(cuuint64_t)K_CAT, (cuuint64_t)OUT_DIM};
        cuuint64_t strides[1] = {(cuuint64_t)K_CAT * 2};
        cuuint32_t box[2]     = {BK, TILE_N};
        cuuint32_t es[2]      = {1, 1};
        encode(&s_tma_b, CU_TENSOR_MAP_DATA_TYPE_FLOAT16, 2, wa,
               dims, strides, box, es,
               CU_TENSOR_MAP_INTERLEAVE_NONE, CU_TENSOR_MAP_SWIZZLE_128B,
               CU_TENSOR_MAP_L2_PROMOTION_L2_128B,
               CU_TENSOR_MAP_FLOAT_OOB_FILL_NONE);
    }
}

extern "C" void kernel_launch(void* const* d_in, const int* in_sizes, int n_in,
                              void* d_out, int out_size) {
    const float* x = (const float*)d_in[0];   // [T, B, IN]
    const float* w = (const float*)d_in[1];   // [OUT, IN]
    float* out = (float*)d_out;               // [T, B, OUT]

    build_tensormaps();
    float* cbuf;
    cudaGetSymbolAddress((void**)&cbuf, g_cur);

    convert_all_kernel<<<XBLKS + WBLKS, 256>>>(x, w);

    cudaFuncSetAttribute(snn_gemm_kernel,
                         cudaFuncAttributeMaxDynamicSharedMemorySize, SMEM_BYTES);
    snn_gemm_kernel<<<(M_TOTAL / TILE_M) * (OUT_DIM / TILE_N), NTH, SMEM_BYTES>>>(
        s_tma_a, s_tma_b, cbuf);

    lif_scan_kernel<<<(int)((size_t)BATCH * OUT_DIM / 4 / 256), 256>>>(cbuf, out);
}